// round 8
// baseline (speedup 1.0000x reference)
#include <cuda_runtime.h>
#include <cstdint>

#define B_ 32
#define T_ 64
#define D_ 32
#define H_ 256
#define Z_ 64
#define G_ 768   // 3*H

// ---------------- scratch (static device memory; no allocations) ----------------
__device__ float g_WencT[H_ * G_];        // enc_Whh transposed: [k][g]
__device__ float g_WihTenc[D_ * G_];      // enc_Wih transposed: [d][g]
__device__ float g_WhhT[D_ * H_ * G_];    // per-head h_Whh transposed: [head][k][g]
__device__ float g_Weff[D_ * D_ * G_];    // folded input weights: [head][d][g]
__device__ float g_henc[B_ * H_];         // encoder final hidden
__device__ float g_h0[B_ * H_];           // decoder initial hidden

// ---------------- fast, sufficiently-accurate activations ----------------
__device__ __forceinline__ float fsigmoid(float x) {
    float e = __expf(-x);                       // MUFU.EX2-based, ~1e-6 rel err
    return __fdividef(1.f, 1.f + e);            // e=inf -> 0 (correct saturation)
}
__device__ __forceinline__ float ftanh(float x) {
    float e = __expf(2.f * x);
    return 1.f - __fdividef(2.f, e + 1.f);      // e=inf -> 1, e=0 -> -1 (no NaN)
}

// ---------------- prep: weight transposes ----------------
__global__ void prep_kernel(const float* __restrict__ enc_Whh,
                            const float* __restrict__ enc_Wih,
                            const float* __restrict__ h_Whh) {
    const int total = H_ * G_ + D_ * G_ + D_ * H_ * G_;
    for (int idx = blockIdx.x * blockDim.x + threadIdx.x; idx < total;
         idx += gridDim.x * blockDim.x) {
        if (idx < H_ * G_) {
            int k = idx / G_, g = idx % G_;
            g_WencT[idx] = enc_Whh[g * H_ + k];
        } else if (idx < H_ * G_ + D_ * G_) {
            int r = idx - H_ * G_;
            int d = r / G_, g = r % G_;
            g_WihTenc[r] = enc_Wih[g * D_ + d];
        } else {
            int r = idx - (H_ * G_ + D_ * G_);
            int head = r / (H_ * G_);
            int rr = r % (H_ * G_);
            int k = rr / G_, g = rr % G_;
            g_WhhT[r] = h_Whh[head * (G_ * H_) + g * H_ + k];
        }
    }
}

// ---------------- Weff[head][d][g] = sum_k Win[head][d][k] * h_Wih[head][g][k] ----------------
__global__ void __launch_bounds__(256) weff_kernel(const float* __restrict__ Win,
                                                   const float* __restrict__ h_Wih) {
    const int head = blockIdx.x;
    const int g = blockIdx.y * 256 + threadIdx.x;   // blockIdx.y in [0,3)
    __shared__ float win_s[D_ * H_];                // 32 KB
    for (int i = threadIdx.x; i < D_ * H_; i += 256)
        win_s[i] = Win[head * (D_ * H_) + i];
    __syncthreads();

    float acc[D_];
#pragma unroll
    for (int d = 0; d < D_; d++) acc[d] = 0.f;

    const float* wih = h_Wih + (size_t)head * (G_ * H_) + (size_t)g * H_;
    for (int k = 0; k < H_; k++) {
        float wv = __ldg(&wih[k]);
#pragma unroll
        for (int d = 0; d < D_; d++) acc[d] += win_s[d * H_ + k] * wv;
    }
    float* o = g_Weff + head * (D_ * G_);
#pragma unroll
    for (int d = 0; d < D_; d++) o[d * G_ + g] = acc[d];
}

// ---------------- encoder GRU: one CTA per batch row ----------------
__global__ void __launch_bounds__(256) encoder_kernel(const float* __restrict__ x_past,
                                                      const float* __restrict__ bih,
                                                      const float* __restrict__ bhh) {
    const int b = blockIdx.x;
    const int j = threadIdx.x;                    // hidden unit owned by this thread
    __shared__ float h_s[2][H_];
    __shared__ float x_s[D_];

    const float br  = bih[j] + bhh[j];
    const float bz  = bih[H_ + j] + bhh[H_ + j];
    const float bin = bih[2 * H_ + j];
    const float bhn = bhh[2 * H_ + j];

    float hp = 0.f;
    h_s[0][j] = 0.f;
    int cur = 0;

    for (int t = 0; t < T_; t++) {
        __syncthreads();
        if (j < D_) x_s[j] = x_past[(b * T_ + t) * D_ + j];
        __syncthreads();

        float ar = br, az = bz, ain = bin, ahn = bhn;
#pragma unroll 4
        for (int d = 0; d < D_; d++) {
            float xv = x_s[d];
            const float* w = &g_WihTenc[d * G_ + j];
            ar  += w[0]      * xv;
            az  += w[H_]     * xv;
            ain += w[2 * H_] * xv;
        }
#pragma unroll 4
        for (int k = 0; k < H_; k++) {
            float hk = h_s[cur][k];
            const float* w = &g_WencT[k * G_ + j];
            ar  += w[0]      * hk;
            az  += w[H_]     * hk;
            ahn += w[2 * H_] * hk;
        }
        float r = fsigmoid(ar);
        float u = fsigmoid(az);
        float n = ftanh(ain + r * ahn);
        hp = n + u * (hp - n);
        cur ^= 1;
        h_s[cur][j] = hp;
    }
    g_henc[b * H_ + j] = hp;
}

// ---------------- latent: mu, logsig, z, h0; writes mu/logsig to out ----------------
__global__ void __launch_bounds__(256) latent_kernel(const float* __restrict__ eps,
                                                     const float* __restrict__ mu_w,
                                                     const float* __restrict__ mu_b,
                                                     const float* __restrict__ ls_w,
                                                     const float* __restrict__ ls_b,
                                                     const float* __restrict__ refc_w,
                                                     const float* __restrict__ refc_b,
                                                     float* __restrict__ out) {
    const int b = blockIdx.x;
    const int j = threadIdx.x;
    __shared__ float h_l[H_];
    __shared__ float z_s[Z_];

    h_l[j] = g_henc[b * H_ + j];
    __syncthreads();

    if (j < Z_) {
        float m = mu_b[j], l = ls_b[j];
        for (int k = 0; k < H_; k++) {
            float hv = h_l[k];
            m += mu_w[j * H_ + k] * hv;
            l += ls_w[j * H_ + k] * hv;
        }
        out[B_ * T_ * D_ + b * Z_ + j] = m;                 // mu
        out[B_ * T_ * D_ + B_ * Z_ + b * Z_ + j] = l;       // logsig
        z_s[j] = m + eps[b * Z_ + j] * __expf(l);
    }
    __syncthreads();

    float a = refc_b[j];
#pragma unroll 4
    for (int z = 0; z < Z_; z++) a += refc_w[j * Z_ + z] * z_s[z];
    g_h0[b * H_ + j] = ftanh(a);
}

// ---------------- fused decoder: 32 heads x 4 batch-groups of 8 ----------------
__global__ void __launch_bounds__(256) decoder_kernel(const float* __restrict__ x_past,
                                                      const float* __restrict__ x_current,
                                                      const float* __restrict__ h_bih,
                                                      const float* __restrict__ h_bhh,
                                                      const float* __restrict__ fc_w,
                                                      const float* __restrict__ fc_b,
                                                      float* __restrict__ out) {
    const int head = blockIdx.x;
    const int b0 = blockIdx.y * 8;
    const int j = threadIdx.x;                  // hidden unit
    const int lane = j & 31, warp = j >> 5;

    __shared__ __align__(16) float h_s[2][H_][8];   // [buf][k][batch]
    __shared__ __align__(16) float dec_s[D_][8];    // [d][batch]
    __shared__ float red_s[8][8];                   // [warp][batch]

    const float* bih = h_bih + head * G_;
    const float* bhh = h_bhh + head * G_;
    const float br  = bih[j] + bhh[j];
    const float bz  = bih[H_ + j] + bhh[H_ + j];
    const float bin = bih[2 * H_ + j];
    const float bhn = bhh[2 * H_ + j];
    const float fcw = fc_w[head * H_ + j];
    const float fcbv = fc_b[head];

    float hp[8];
#pragma unroll
    for (int bb = 0; bb < 8; bb++) {
        hp[bb] = g_h0[(b0 + bb) * H_ + j];
        h_s[0][j][bb] = hp[bb];
    }

    const float* Weff = g_Weff + head * (D_ * G_);
    const float* WhhT = g_WhhT + (size_t)head * (H_ * G_);
    int cur = 0;

    for (int t = 0; t < T_; t++) {
        __syncthreads();                         // h_s[cur] ready; dec_s/red_s reusable
        {
            int d = j >> 3, bb = j & 7;          // 256 threads cover 32x8
            float v;
            if (t == 0) v = x_past[((b0 + bb) * T_ + (T_ - 1)) * D_ + d];
            else        v = x_current[((b0 + bb) * T_ + (t - 1)) * D_ + d];
            dec_s[d][bb] = v;
        }
        __syncthreads();

        float ar[8], az[8], ain[8], ahn[8];
#pragma unroll
        for (int bb = 0; bb < 8; bb++) { ar[bb] = br; az[bb] = bz; ain[bb] = bin; ahn[bb] = bhn; }

        // gi (folded input projection): 32 d-iters
#pragma unroll 4
        for (int d = 0; d < D_; d++) {
            const float* w = &Weff[d * G_ + j];
            float wr = w[0], wz = w[H_], wn = w[2 * H_];
            float4 v0 = *(const float4*)&dec_s[d][0];
            float4 v1 = *(const float4*)&dec_s[d][4];
            float xv[8] = {v0.x, v0.y, v0.z, v0.w, v1.x, v1.y, v1.z, v1.w};
#pragma unroll
            for (int bb = 0; bb < 8; bb++) {
                ar[bb]  += wr * xv[bb];
                az[bb]  += wz * xv[bb];
                ain[bb] += wn * xv[bb];
            }
        }

        // gh (recurrent matmul): 256 k-iters, weights streamed coalesced from L2
#pragma unroll 4
        for (int k = 0; k < H_; k++) {
            const float* w = &WhhT[k * G_ + j];
            float wr = w[0], wz = w[H_], wn = w[2 * H_];
            float4 v0 = *(const float4*)&h_s[cur][k][0];
            float4 v1 = *(const float4*)&h_s[cur][k][4];
            float hv[8] = {v0.x, v0.y, v0.z, v0.w, v1.x, v1.y, v1.z, v1.w};
#pragma unroll
            for (int bb = 0; bb < 8; bb++) {
                ar[bb]  += wr * hv[bb];
                az[bb]  += wz * hv[bb];
                ahn[bb] += wn * hv[bb];
            }
        }

        // gates + fc partials
        float p[8];
#pragma unroll
        for (int bb = 0; bb < 8; bb++) {
            float r = fsigmoid(ar[bb]);
            float u = fsigmoid(az[bb]);
            float n = ftanh(ain[bb] + r * ahn[bb]);
            float hn = n + u * (hp[bb] - n);
            hp[bb] = hn;
            p[bb] = fcw * hn;
        }
        *(float4*)&h_s[cur ^ 1][j][0] = make_float4(hp[0], hp[1], hp[2], hp[3]);
        *(float4*)&h_s[cur ^ 1][j][4] = make_float4(hp[4], hp[5], hp[6], hp[7]);

        // fc reduction: warp shfl then cross-warp via smem
#pragma unroll
        for (int bb = 0; bb < 8; bb++) {
#pragma unroll
            for (int off = 16; off > 0; off >>= 1)
                p[bb] += __shfl_down_sync(0xffffffffu, p[bb], off);
        }
        if (lane == 0) {
#pragma unroll
            for (int bb = 0; bb < 8; bb++) red_s[warp][bb] = p[bb];
        }
        __syncthreads();
        if (j < 8) {
            float s = fcbv;
#pragma unroll
            for (int w = 0; w < 8; w++) s += red_s[w][j];
            out[((b0 + j) * T_ + t) * D_ + head] = s;
        }
        cur ^= 1;
    }
}

// ---------------- launch ----------------
extern "C" void kernel_launch(void* const* d_in, const int* in_sizes, int n_in,
                              void* d_out, int out_size) {
    (void)in_sizes; (void)n_in; (void)out_size;
    const float* x_past    = (const float*)d_in[0];
    const float* x_current = (const float*)d_in[1];
    const float* eps       = (const float*)d_in[2];
    const float* enc_Wih   = (const float*)d_in[3];
    const float* enc_bih   = (const float*)d_in[4];
    const float* enc_Whh   = (const float*)d_in[5];
    const float* enc_bhh   = (const float*)d_in[6];
    const float* enc_mu_w  = (const float*)d_in[7];
    const float* enc_mu_b  = (const float*)d_in[8];
    const float* enc_ls_w  = (const float*)d_in[9];
    const float* enc_ls_b  = (const float*)d_in[10];
    const float* refc_w    = (const float*)d_in[11];
    const float* refc_b    = (const float*)d_in[12];
    const float* Win       = (const float*)d_in[13];
    const float* h_Wih     = (const float*)d_in[14];
    const float* h_bih     = (const float*)d_in[15];
    const float* h_Whh     = (const float*)d_in[16];
    const float* h_bhh     = (const float*)d_in[17];
    const float* fc_w      = (const float*)d_in[18];
    const float* fc_b      = (const float*)d_in[19];
    float* out = (float*)d_out;

    const int total = H_ * G_ + D_ * G_ + D_ * H_ * G_;
    prep_kernel<<<(total + 255) / 256, 256>>>(enc_Whh, enc_Wih, h_Whh);
    weff_kernel<<<dim3(32, 3), 256>>>(Win, h_Wih);
    encoder_kernel<<<32, 256>>>(x_past, enc_bih, enc_bhh);
    latent_kernel<<<32, 256>>>(eps, enc_mu_w, enc_mu_b, enc_ls_w, enc_ls_b,
                               refc_w, refc_b, out);
    decoder_kernel<<<dim3(32, 4), 256>>>(x_past, x_current, h_bih, h_bhh,
                                         fc_w, fc_b, out);
}

// round 9
// speedup vs baseline: 1.2385x; 1.2385x over previous
#include <cuda_runtime.h>
#include <cstdint>

#define B_ 32
#define T_ 64
#define D_ 32
#define H_ 256
#define Z_ 64
#define G_ 768   // 3*H

// ---------------- scratch (static device memory; no allocations) ----------------
__device__ float g_WhhQ[D_ * H_ * H_ * 4];   // decoder recurrent, interleaved [head][k][j][{r,z,n,0}]
__device__ float g_WeQ [H_ * H_ * 4];        // encoder recurrent, interleaved [k][j][{r,z,n,0}]
__device__ float g_WiQ [D_ * H_ * 4];        // encoder input,    interleaved [d][j][{r,z,n,0}]
__device__ float g_WihT[D_ * H_ * G_];       // h_Wih transposed planar: [head][k][g]
__device__ float g_WeffQ[D_ * D_ * H_ * 4];  // folded input weights, interleaved [head][d][j][{r,z,n,0}]
__device__ float g_muT [H_ * Z_];            // enc_mu_w transposed [k][z]
__device__ float g_lsT [H_ * Z_];            // enc_ls_w transposed [k][z]
__device__ float g_refcT[Z_ * H_];           // refc_w transposed [z][j]
__device__ float g_h0  [B_ * H_];            // decoder initial hidden

// ---------------- fast, sufficiently-accurate activations ----------------
__device__ __forceinline__ float fsigmoid(float x) {
    float e = __expf(-x);
    return __fdividef(1.f, 1.f + e);
}
__device__ __forceinline__ float ftanh(float x) {
    float e = __expf(2.f * x);
    return 1.f - __fdividef(2.f, e + 1.f);
}

// ---------------- prep: tiled transposes ----------------
// Blocks:
//   [0,512)     : h_Whh  -> g_WhhQ  (float4 interleave)   head = bx>>4, jt=(bx>>2)&3, kt=bx&3
//   [512,1024)  : h_Wih  -> g_WihT  (planar [k][g])
//   [1024,1040) : enc_Whh-> g_WeQ   (float4 interleave)
//   [1040]      : small transposes: g_WiQ, g_muT, g_lsT, g_refcT
__global__ void __launch_bounds__(256) prep_kernel(const float* __restrict__ h_Whh,
                                                   const float* __restrict__ h_Wih,
                                                   const float* __restrict__ enc_Whh,
                                                   const float* __restrict__ enc_Wih,
                                                   const float* __restrict__ mu_w,
                                                   const float* __restrict__ ls_w,
                                                   const float* __restrict__ refc_w) {
    const int bx = blockIdx.x;
    const int tid = threadIdx.x;

    if (bx < 1040) {
        __shared__ float tile[3][64][64];   // XOR-swizzled: [g][jj][(kk+jj)&63], 48KB
        const float* src;
        int jt, kt, mode;                   // mode 0: float4 interleave out, 1: planar out
        float4* dst4 = nullptr;
        float*  dstp = nullptr;
        if (bx < 512) {
            int head = bx >> 4; jt = (bx >> 2) & 3; kt = bx & 3; mode = 0;
            src = h_Whh + (size_t)head * (G_ * H_);
            dst4 = ((float4*)g_WhhQ) + (size_t)head * (H_ * H_);
        } else if (bx < 1024) {
            int e = bx - 512;
            int head = e >> 4; jt = (e >> 2) & 3; kt = e & 3; mode = 1;
            src = h_Wih + (size_t)head * (G_ * H_);
            dstp = g_WihT + (size_t)head * (H_ * G_);
        } else {
            int e = bx - 1024;
            jt = (e >> 2) & 3; kt = e & 3; mode = 0;
            src = enc_Whh;
            dst4 = (float4*)g_WeQ;
        }
        // read phase: coalesced along k
        for (int g = 0; g < 3; g++) {
            for (int i = tid; i < 64 * 64; i += 256) {
                int jj = i >> 6, kk = i & 63;
                tile[g][jj][(kk + jj) & 63] =
                    src[(size_t)(g * H_ + jt * 64 + jj) * H_ + kt * 64 + kk];
            }
        }
        __syncthreads();
        // write phase: coalesced along j
        if (mode == 0) {
            for (int i = tid; i < 64 * 64; i += 256) {
                int kk = i >> 6, jj = i & 63;
                float4 w = make_float4(tile[0][jj][(kk + jj) & 63],
                                       tile[1][jj][(kk + jj) & 63],
                                       tile[2][jj][(kk + jj) & 63], 0.f);
                dst4[(size_t)(kt * 64 + kk) * H_ + jt * 64 + jj] = w;
            }
        } else {
            for (int g = 0; g < 3; g++) {
                for (int i = tid; i < 64 * 64; i += 256) {
                    int kk = i >> 6, jj = i & 63;
                    dstp[(size_t)(kt * 64 + kk) * G_ + g * H_ + jt * 64 + jj] =
                        tile[g][jj][(kk + jj) & 63];
                }
            }
        }
    } else {
        // small transposes (one block, grid-stride)
        float4* wiq = (float4*)g_WiQ;
        for (int i = tid; i < D_ * H_; i += 256) {          // g_WiQ[d][j]
            int d = i >> 8, j = i & 255;
            wiq[i] = make_float4(enc_Wih[(0 * H_ + j) * D_ + d],
                                 enc_Wih[(1 * H_ + j) * D_ + d],
                                 enc_Wih[(2 * H_ + j) * D_ + d], 0.f);
        }
        for (int i = tid; i < H_ * Z_; i += 256) {          // muT/lsT[k][z]
            int k = i >> 6, z = i & 63;
            g_muT[i] = mu_w[z * H_ + k];
            g_lsT[i] = ls_w[z * H_ + k];
        }
        for (int i = tid; i < Z_ * H_; i += 256) {          // refcT[z][j]
            int z = i >> 8, j = i & 255;
            g_refcT[i] = refc_w[j * Z_ + z];
        }
    }
}

// ---------------- Weff[head][d][j][gate] = sum_k Win[head][d][k] * h_Wih[head][g][k] ----------------
__global__ void __launch_bounds__(256) weff_kernel(const float* __restrict__ Win) {
    const int head = blockIdx.x;
    const int g = blockIdx.y * 256 + threadIdx.x;    // blockIdx.y in [0,3)
    __shared__ float win_s[D_ * H_];                 // 32 KB
    for (int i = threadIdx.x; i < D_ * H_; i += 256)
        win_s[i] = Win[head * (D_ * H_) + i];
    __syncthreads();

    float acc[D_];
#pragma unroll
    for (int d = 0; d < D_; d++) acc[d] = 0.f;

    const float* wt = g_WihT + (size_t)head * (H_ * G_);
#pragma unroll 4
    for (int k = 0; k < H_; k++) {
        float wv = wt[(size_t)k * G_ + g];           // coalesced
#pragma unroll
        for (int d = 0; d < D_; d++) acc[d] += win_s[d * H_ + k] * wv;
    }
    const int gate = g >> 8, jj = g & 255;
    float* o = g_WeffQ + (size_t)head * (D_ * H_ * 4);
#pragma unroll
    for (int d = 0; d < D_; d++) o[(d * H_ + jj) * 4 + gate] = acc[d];
}

// ---------------- encoder GRU + latent (fused): one CTA per batch row ----------------
__global__ void __launch_bounds__(256) encoder_kernel(const float* __restrict__ x_past,
                                                      const float* __restrict__ bih,
                                                      const float* __restrict__ bhh,
                                                      const float* __restrict__ eps,
                                                      const float* __restrict__ mu_b,
                                                      const float* __restrict__ ls_b,
                                                      const float* __restrict__ refc_b,
                                                      float* __restrict__ out) {
    const int b = blockIdx.x;
    const int j = threadIdx.x;
    __shared__ float h_s[2][H_];
    __shared__ float x_s[D_];
    __shared__ float z_s[Z_];

    const float br  = bih[j] + bhh[j];
    const float bz  = bih[H_ + j] + bhh[H_ + j];
    const float bin = bih[2 * H_ + j];
    const float bhn = bhh[2 * H_ + j];

    const float4* WiQ4 = (const float4*)g_WiQ;
    const float4* WeQ4 = (const float4*)g_WeQ;

    float hp = 0.f;
    h_s[0][j] = 0.f;
    int cur = 0;

    for (int t = 0; t < T_; t++) {
        __syncthreads();
        if (j < D_) x_s[j] = x_past[(b * T_ + t) * D_ + j];
        __syncthreads();

        float ar = br, az = bz, ain = bin, ahn = bhn;
#pragma unroll 8
        for (int d = 0; d < D_; d++) {
            float4 w = WiQ4[d * H_ + j];
            float xv = x_s[d];
            ar += w.x * xv; az += w.y * xv; ain += w.z * xv;
        }
#pragma unroll 8
        for (int k = 0; k < H_; k++) {
            float4 w = WeQ4[k * H_ + j];
            float hk = h_s[cur][k];
            ar += w.x * hk; az += w.y * hk; ahn += w.z * hk;
        }
        float r = fsigmoid(ar);
        float u = fsigmoid(az);
        float n = ftanh(ain + r * ahn);
        hp = n + u * (hp - n);
        cur ^= 1;
        h_s[cur][j] = hp;
    }
    __syncthreads();

    // --- latent (fused): mu/logsig/z/h0 ---
    if (j < Z_) {
        float m = mu_b[j], l = ls_b[j];
#pragma unroll 8
        for (int k = 0; k < H_; k++) {
            float hv = h_s[cur][k];
            m += g_muT[k * Z_ + j] * hv;
            l += g_lsT[k * Z_ + j] * hv;
        }
        out[B_ * T_ * D_ + b * Z_ + j] = m;                    // mu
        out[B_ * T_ * D_ + B_ * Z_ + b * Z_ + j] = l;          // logsig
        z_s[j] = m + eps[b * Z_ + j] * __expf(l);
    }
    __syncthreads();

    float a = refc_b[j];
#pragma unroll 8
    for (int z = 0; z < Z_; z++) a += g_refcT[z * H_ + j] * z_s[z];
    g_h0[b * H_ + j] = ftanh(a);
}

// ---------------- fused decoder: 32 heads x 4 batch-groups of 8, 512 threads ----------------
// thread = (j = tid&255, batch-half = tid>>8); each thread owns 4 batch rows.
__global__ void __launch_bounds__(512) decoder_kernel(const float* __restrict__ x_past,
                                                      const float* __restrict__ x_current,
                                                      const float* __restrict__ h_bih,
                                                      const float* __restrict__ h_bhh,
                                                      const float* __restrict__ fc_w,
                                                      const float* __restrict__ fc_b,
                                                      float* __restrict__ out) {
    const int head = blockIdx.x;
    const int b0 = blockIdx.y * 8;
    const int tid = threadIdx.x;
    const int j = tid & 255;
    const int bh4 = (tid >> 8) * 4;              // 0 or 4
    const int lane = tid & 31, warp = tid >> 5;  // warps 0-7: batches b0..b0+3; 8-15: b0+4..b0+7

    __shared__ __align__(16) float h_s[2][H_][8];   // [buf][k][batch] 16KB
    __shared__ __align__(16) float dec_s[D_][8];    // [d][batch]
    __shared__ float red_s[16][4];                  // [warp][local batch]

    const float* bih = h_bih + head * G_;
    const float* bhh = h_bhh + head * G_;
    const float br  = bih[j] + bhh[j];
    const float bz  = bih[H_ + j] + bhh[H_ + j];
    const float bin = bih[2 * H_ + j];
    const float bhn = bhh[2 * H_ + j];
    const float fcw = fc_w[head * H_ + j];
    const float fcbv = fc_b[head];

    float hp[4];
#pragma unroll
    for (int bb = 0; bb < 4; bb++) hp[bb] = g_h0[(b0 + bh4 + bb) * H_ + j];
    *(float4*)&h_s[0][j][bh4] = make_float4(hp[0], hp[1], hp[2], hp[3]);

    const float4* Wq = ((const float4*)g_WhhQ)  + (size_t)head * (H_ * H_);
    const float4* Eq = ((const float4*)g_WeffQ) + (size_t)head * (D_ * H_);
    int cur = 0;

    for (int t = 0; t < T_; t++) {
        if (tid < 256) {
            int d = tid >> 3, bb = tid & 7;
            float v;
            if (t == 0) v = x_past[((b0 + bb) * T_ + (T_ - 1)) * D_ + d];
            else        v = x_current[((b0 + bb) * T_ + (t - 1)) * D_ + d];
            dec_s[d][bb] = v;
        }
        __syncthreads();    // dec_s ready; h_s[cur] ready (writes before prior sync)

        float ar[4], az[4], ain[4], ahn[4];
#pragma unroll
        for (int bb = 0; bb < 4; bb++) { ar[bb] = br; az[bb] = bz; ain[bb] = bin; ahn[bb] = bhn; }

        // gi: folded input projection (32 iters, 1 LDG.128 + broadcast LDS.128 + 12 FFMA)
#pragma unroll 8
        for (int d = 0; d < D_; d++) {
            float4 w  = Eq[d * H_ + j];
            float4 x4 = *(const float4*)&dec_s[d][bh4];
            float xv[4] = {x4.x, x4.y, x4.z, x4.w};
#pragma unroll
            for (int bb = 0; bb < 4; bb++) {
                ar[bb]  += w.x * xv[bb];
                az[bb]  += w.y * xv[bb];
                ain[bb] += w.z * xv[bb];
            }
        }

        // gh: recurrent matmul (256 iters, 1 LDG.128 + broadcast LDS.128 + 12 FFMA)
#pragma unroll 8
        for (int k = 0; k < H_; k++) {
            float4 w  = Wq[k * H_ + j];
            float4 h4 = *(const float4*)&h_s[cur][k][bh4];
            float hv[4] = {h4.x, h4.y, h4.z, h4.w};
#pragma unroll
            for (int bb = 0; bb < 4; bb++) {
                ar[bb]  += w.x * hv[bb];
                az[bb]  += w.y * hv[bb];
                ahn[bb] += w.z * hv[bb];
            }
        }

        // gates + fc partials
        float p[4];
#pragma unroll
        for (int bb = 0; bb < 4; bb++) {
            float r = fsigmoid(ar[bb]);
            float u = fsigmoid(az[bb]);
            float n = ftanh(ain[bb] + r * ahn[bb]);
            float hn = n + u * (hp[bb] - n);
            hp[bb] = hn;
            p[bb] = fcw * hn;
        }
        *(float4*)&h_s[cur ^ 1][j][bh4] = make_float4(hp[0], hp[1], hp[2], hp[3]);

        // fc reduction: intra-warp shfl, then cross-warp via smem
#pragma unroll
        for (int bb = 0; bb < 4; bb++) {
#pragma unroll
            for (int off = 16; off > 0; off >>= 1)
                p[bb] += __shfl_down_sync(0xffffffffu, p[bb], off);
        }
        if (lane == 0) {
#pragma unroll
            for (int bb = 0; bb < 4; bb++) red_s[warp][bb] = p[bb];
        }
        __syncthreads();
        if (tid < 8) {
            int w0 = (tid < 4) ? 0 : 8;
            int col = tid & 3;
            float s = fcbv;
#pragma unroll
            for (int w = 0; w < 8; w++) s += red_s[w0 + w][col];
            out[((b0 + tid) * T_ + t) * D_ + head] = s;
        }
        cur ^= 1;
    }
}

// ---------------- launch ----------------
extern "C" void kernel_launch(void* const* d_in, const int* in_sizes, int n_in,
                              void* d_out, int out_size) {
    (void)in_sizes; (void)n_in; (void)out_size;
    const float* x_past    = (const float*)d_in[0];
    const float* x_current = (const float*)d_in[1];
    const float* eps       = (const float*)d_in[2];
    const float* enc_Wih   = (const float*)d_in[3];
    const float* enc_bih   = (const float*)d_in[4];
    const float* enc_Whh   = (const float*)d_in[5];
    const float* enc_bhh   = (const float*)d_in[6];
    const float* enc_mu_w  = (const float*)d_in[7];
    const float* enc_mu_b  = (const float*)d_in[8];
    const float* enc_ls_w  = (const float*)d_in[9];
    const float* enc_ls_b  = (const float*)d_in[10];
    const float* refc_w    = (const float*)d_in[11];
    const float* refc_b    = (const float*)d_in[12];
    const float* Win       = (const float*)d_in[13];
    const float* h_Wih     = (const float*)d_in[14];
    const float* h_bih     = (const float*)d_in[15];
    const float* h_Whh     = (const float*)d_in[16];
    const float* h_bhh     = (const float*)d_in[17];
    const float* fc_w      = (const float*)d_in[18];
    const float* fc_b      = (const float*)d_in[19];
    float* out = (float*)d_out;

    prep_kernel<<<1041, 256>>>(h_Whh, h_Wih, enc_Whh, enc_Wih, enc_mu_w, enc_ls_w, refc_w);
    weff_kernel<<<dim3(32, 3), 256>>>(Win);
    encoder_kernel<<<32, 256>>>(x_past, enc_bih, enc_bhh, eps, enc_mu_b, enc_ls_b,
                                refc_b, out);
    decoder_kernel<<<dim3(32, 4), 512>>>(x_past, x_current, h_bih, h_bhh,
                                         fc_w, fc_b, out);
}

// round 10
// speedup vs baseline: 3.4409x; 2.7782x over previous
#include <cuda_runtime.h>
#include <cstdint>

#define B_ 32
#define T_ 64
#define D_ 32
#define H_ 256
#define Z_ 64
#define G_ 768   // 3*H
#define KP_ 128  // H_/2 (k-pairs)

typedef unsigned long long ull;

// ---------------- scratch (static device memory; no allocations) ----------------
// decoder recurrent weights, pad-free, k-paired:
//   g_Wrz4[head][kp][j] = (r_{2kp}, z_{2kp}, r_{2kp+1}, z_{2kp+1})
//   g_Wn2 [head][kp][j] = (n_{2kp}, n_{2kp+1})
__device__ float4 g_Wrz4[D_ * KP_ * H_ + 8 * H_];
__device__ float2 g_Wn2 [D_ * KP_ * H_ + 8 * H_];
// encoder recurrent, same layout
__device__ float4 g_Erz4[KP_ * H_ + 8 * H_];
__device__ float2 g_En2 [KP_ * H_ + 8 * H_];
__device__ float4 g_WiQ [D_ * H_];            // encoder input: [d][j] = (r,z,n,0)
__device__ float  g_WihT[D_ * H_ * G_];       // h_Wih transposed planar: [head][k][g]
__device__ float4 g_Weff4[D_ * D_ * H_ + 4 * H_]; // folded input: [head][d][j] = (r,z,n,0)
__device__ float  g_muT [H_ * Z_];            // enc_mu_w transposed [k][z]
__device__ float  g_lsT [H_ * Z_];            // enc_ls_w transposed [k][z]
__device__ float  g_refcT[Z_ * H_];           // refc_w transposed [z][j]
__device__ float  g_h0  [B_ * H_];            // decoder initial hidden

// ---------------- packed f32x2 helpers ----------------
__device__ __forceinline__ void fma2(ull& d, ull a, ull b) {
    asm("fma.rn.f32x2 %0, %1, %2, %0;" : "+l"(d) : "l"(a), "l"(b));
}
__device__ __forceinline__ ull splat2(float x) {
    ull r; unsigned u = __float_as_uint(x);
    asm("mov.b64 %0, {%1, %1};" : "=l"(r) : "r"(u));
    return r;
}
__device__ __forceinline__ ull pack2(float a, float b) {
    ull r;
    asm("mov.b64 %0, {%1, %2};" : "=l"(r) : "r"(__float_as_uint(a)), "r"(__float_as_uint(b)));
    return r;
}
__device__ __forceinline__ ull splat_u(unsigned u) {
    ull r;
    asm("mov.b64 %0, {%1, %1};" : "=l"(r) : "r"(u));
    return r;
}
__device__ __forceinline__ float lo_f(ull v) { return __uint_as_float((unsigned)v); }
__device__ __forceinline__ float hi_f(ull v) { return __uint_as_float((unsigned)(v >> 32)); }
__device__ __forceinline__ unsigned lo_u(ull v) { return (unsigned)v; }
__device__ __forceinline__ unsigned hi_u(ull v) { return (unsigned)(v >> 32); }

// ---------------- fast activations ----------------
__device__ __forceinline__ float fsigmoid(float x) {
    float e = __expf(-x);
    return __fdividef(1.f, 1.f + e);
}
__device__ __forceinline__ float ftanh(float x) {
    float e = __expf(2.f * x);
    return 1.f - __fdividef(2.f, e + 1.f);
}

// ---------------- prep: tiled transposes into paired-split layouts ----------------
// Blocks:
//   [0,512)     : h_Whh  -> g_Wrz4/g_Wn2   head=bx>>4, jt=(bx>>2)&3, kt=bx&3
//   [512,1024)  : h_Wih  -> g_WihT (planar [k][g])
//   [1024,1040) : enc_Whh-> g_Erz4/g_En2
//   [1040]      : small transposes: g_WiQ, g_muT, g_lsT, g_refcT
__global__ void __launch_bounds__(256) prep_kernel(const float* __restrict__ h_Whh,
                                                   const float* __restrict__ h_Wih,
                                                   const float* __restrict__ enc_Whh,
                                                   const float* __restrict__ enc_Wih,
                                                   const float* __restrict__ mu_w,
                                                   const float* __restrict__ ls_w,
                                                   const float* __restrict__ refc_w) {
    const int bx = blockIdx.x;
    const int tid = threadIdx.x;

    if (bx < 1040) {
        __shared__ float tile[3][64][64];   // XOR-swizzled: [g][jj][(kk+jj)&63], 48KB
        const float* src;
        int jt, kt, mode;                   // mode 0: paired-split out, 1: planar out
        float4* drz = nullptr; float2* dn2 = nullptr;
        float*  dstp = nullptr;
        if (bx < 512) {
            int head = bx >> 4; jt = (bx >> 2) & 3; kt = bx & 3; mode = 0;
            src = h_Whh + (size_t)head * (G_ * H_);
            drz = g_Wrz4 + (size_t)head * (KP_ * H_);
            dn2 = g_Wn2  + (size_t)head * (KP_ * H_);
        } else if (bx < 1024) {
            int e = bx - 512;
            int head = e >> 4; jt = (e >> 2) & 3; kt = e & 3; mode = 1;
            src = h_Wih + (size_t)head * (G_ * H_);
            dstp = g_WihT + (size_t)head * (H_ * G_);
        } else {
            int e = bx - 1024;
            jt = (e >> 2) & 3; kt = e & 3; mode = 0;
            src = enc_Whh;
            drz = g_Erz4; dn2 = g_En2;
        }
        // read phase: coalesced along k
        for (int g = 0; g < 3; g++) {
            for (int i = tid; i < 64 * 64; i += 256) {
                int jj = i >> 6, kk = i & 63;
                tile[g][jj][(kk + jj) & 63] =
                    src[(size_t)(g * H_ + jt * 64 + jj) * H_ + kt * 64 + kk];
            }
        }
        __syncthreads();
        // write phase: coalesced along j
        if (mode == 0) {
            for (int i = tid; i < 32 * 64; i += 256) {
                int kkp = i >> 6, jj = i & 63;
                int c0 = (2 * kkp + jj) & 63, c1 = (2 * kkp + 1 + jj) & 63;
                float r0 = tile[0][jj][c0], r1 = tile[0][jj][c1];
                float z0 = tile[1][jj][c0], z1 = tile[1][jj][c1];
                float n0 = tile[2][jj][c0], n1 = tile[2][jj][c1];
                size_t idx = (size_t)(kt * 32 + kkp) * H_ + jt * 64 + jj;
                drz[idx] = make_float4(r0, z0, r1, z1);
                dn2[idx] = make_float2(n0, n1);
            }
        } else {
            for (int g = 0; g < 3; g++) {
                for (int i = tid; i < 64 * 64; i += 256) {
                    int kk = i >> 6, jj = i & 63;
                    dstp[(size_t)(kt * 64 + kk) * G_ + g * H_ + jt * 64 + jj] =
                        tile[g][jj][(kk + jj) & 63];
                }
            }
        }
    } else {
        for (int i = tid; i < D_ * H_; i += 256) {          // g_WiQ[d][j]
            int d = i >> 8, j = i & 255;
            g_WiQ[i] = make_float4(enc_Wih[(0 * H_ + j) * D_ + d],
                                   enc_Wih[(1 * H_ + j) * D_ + d],
                                   enc_Wih[(2 * H_ + j) * D_ + d], 0.f);
        }
        for (int i = tid; i < H_ * Z_; i += 256) {
            int k = i >> 6, z = i & 63;
            g_muT[i] = mu_w[z * H_ + k];
            g_lsT[i] = ls_w[z * H_ + k];
        }
        for (int i = tid; i < Z_ * H_; i += 256) {
            int z = i >> 8, j = i & 255;
            g_refcT[i] = refc_w[j * Z_ + z];
        }
    }
}

// ---------------- Weff[head][d][j] = (r,z,n,0) folded input weights ----------------
__global__ void __launch_bounds__(256) weff_kernel(const float* __restrict__ Win) {
    const int head = blockIdx.x;
    const int g = blockIdx.y * 256 + threadIdx.x;    // blockIdx.y in [0,3)
    __shared__ float win_s[D_ * H_];                 // 32 KB
    for (int i = threadIdx.x; i < D_ * H_; i += 256)
        win_s[i] = Win[head * (D_ * H_) + i];
    __syncthreads();

    float acc[D_];
#pragma unroll
    for (int d = 0; d < D_; d++) acc[d] = 0.f;

    const float* wt = g_WihT + (size_t)head * (H_ * G_);
#pragma unroll 4
    for (int k = 0; k < H_; k++) {
        float wv = wt[(size_t)k * G_ + g];
#pragma unroll
        for (int d = 0; d < D_; d++) acc[d] += win_s[d * H_ + k] * wv;
    }
    const int gate = g >> 8, jj = g & 255;
    float* o = (float*)(g_Weff4 + (size_t)head * (D_ * H_));
#pragma unroll
    for (int d = 0; d < D_; d++) o[(d * H_ + jj) * 4 + gate] = acc[d];
}

// ---------------- encoder GRU + latent (fused): one CTA per batch row ----------------
__global__ void __launch_bounds__(256, 1) encoder_kernel(const float* __restrict__ x_past,
                                                         const float* __restrict__ bih,
                                                         const float* __restrict__ bhh,
                                                         const float* __restrict__ eps,
                                                         const float* __restrict__ mu_b,
                                                         const float* __restrict__ ls_b,
                                                         const float* __restrict__ refc_b,
                                                         float* __restrict__ out) {
    const int b = blockIdx.x;
    const int j = threadIdx.x;
    __shared__ float h_s[2][H_];
    __shared__ float x_s[D_];
    __shared__ float z_s[Z_];

    const float br  = bih[j] + bhh[j];
    const float bz  = bih[H_ + j] + bhh[H_ + j];
    const float bin = bih[2 * H_ + j];
    const float bhn = bhh[2 * H_ + j];
    const ull BRZ = pack2(br, bz);

    const ulonglong2* WiQ2 = (const ulonglong2*)g_WiQ;
    const ulonglong2* wrz0 = ((const ulonglong2*)g_Erz4) + j;
    const ull*        wn0  = ((const ull*)g_En2) + j;

    float hp = 0.f;
    h_s[0][j] = 0.f;
    int cur = 0;

    for (int t = 0; t < T_; t++) {
        __syncthreads();
        if (j < D_) x_s[j] = x_past[(b * T_ + t) * D_ + j];
        __syncthreads();

        ull arz = BRZ;
        float ain = bin, ahn = bhn;

        // gi: 32 iters
#pragma unroll 8
        for (int d = 0; d < D_; d++) {
            ulonglong2 w = WiQ2[d * H_ + j];
            float xv = x_s[d];
            fma2(arz, w.x, splat2(xv));
            ain += lo_f(w.y) * xv;
        }

        // gh: 128 k-pairs, prefetch depth 4
        {
            ulonglong2 brz[4]; ull bn2[4];
#pragma unroll
            for (int i = 0; i < 4; i++) { brz[i] = wrz0[i * H_]; bn2[i] = wn0[i * H_]; }
            const ulonglong2* wpf = wrz0 + 4 * H_;
            const ull*        npf = wn0  + 4 * H_;
            const float* hrow = h_s[cur];
#pragma unroll 1
            for (int kp = 0; kp < KP_; kp += 4) {
#pragma unroll
                for (int u = 0; u < 4; u++) {
                    ulonglong2 w = brz[u]; ull n2 = bn2[u];
                    brz[u] = wpf[u * H_]; bn2[u] = npf[u * H_];
                    float h0 = hrow[(kp + u) * 2];
                    float h1 = hrow[(kp + u) * 2 + 1];
                    fma2(arz, w.x, splat2(h0));
                    fma2(arz, w.y, splat2(h1));
                    ahn += lo_f(n2) * h0;
                    ahn += hi_f(n2) * h1;
                }
                wpf += 4 * H_; npf += 4 * H_;
            }
        }
        float r = fsigmoid(lo_f(arz));
        float u = fsigmoid(hi_f(arz));
        float n = ftanh(ain + r * ahn);
        hp = n + u * (hp - n);
        cur ^= 1;
        h_s[cur][j] = hp;
    }
    __syncthreads();

    // --- latent (fused): mu/logsig/z/h0 ---
    if (j < Z_) {
        float m = mu_b[j], l = ls_b[j];
#pragma unroll 8
        for (int k = 0; k < H_; k++) {
            float hv = h_s[cur][k];
            m += g_muT[k * Z_ + j] * hv;
            l += g_lsT[k * Z_ + j] * hv;
        }
        out[B_ * T_ * D_ + b * Z_ + j] = m;                    // mu
        out[B_ * T_ * D_ + B_ * Z_ + b * Z_ + j] = l;          // logsig
        z_s[j] = m + eps[b * Z_ + j] * __expf(l);
    }
    __syncthreads();

    float a = refc_b[j];
#pragma unroll 8
    for (int z = 0; z < Z_; z++) a += g_refcT[z * H_ + j] * z_s[z];
    g_h0[b * H_ + j] = ftanh(a);
}

// ---------------- fused decoder: 32 heads x 4 batch-groups of 8, 512 threads ----------------
// thread = (j = tid&255, batch-half = tid>>8); each thread owns 4 batch rows.
// Packed f32x2 math: accumulators hold batch-pairs.
__global__ void __launch_bounds__(512, 1) decoder_kernel(const float* __restrict__ x_past,
                                                         const float* __restrict__ x_current,
                                                         const float* __restrict__ h_bih,
                                                         const float* __restrict__ h_bhh,
                                                         const float* __restrict__ fc_w,
                                                         const float* __restrict__ fc_b,
                                                         float* __restrict__ out) {
    const int head = blockIdx.x;
    const int b0 = blockIdx.y * 8;
    const int tid = threadIdx.x;
    const int j = tid & 255;
    const int bh4 = (tid >> 8) * 4;              // 0 or 4
    const int lane = tid & 31, warp = tid >> 5;

    __shared__ __align__(16) float h_s[2][H_][8];   // [buf][k][batch] 16KB
    __shared__ __align__(16) float dec_s[D_][8];    // [d][batch]
    __shared__ float red_s[16][4];                  // [warp][local batch]

    const float* bih = h_bih + head * G_;
    const float* bhh = h_bhh + head * G_;
    const float br  = bih[j] + bhh[j];
    const float bz  = bih[H_ + j] + bhh[H_ + j];
    const float bin = bih[2 * H_ + j];
    const float bhn = bhh[2 * H_ + j];
    const float fcw = fc_w[head * H_ + j];
    const float fcbv = fc_b[head];
    const ull BR = splat2(br), BZ = splat2(bz), BIN = splat2(bin), BHN = splat2(bhn);

    float hp[4];
#pragma unroll
    for (int bb = 0; bb < 4; bb++) hp[bb] = g_h0[(b0 + bh4 + bb) * H_ + j];
    *(float4*)&h_s[0][j][bh4] = make_float4(hp[0], hp[1], hp[2], hp[3]);

    const ulonglong2* Eq   = ((const ulonglong2*)g_Weff4) + (size_t)head * (D_ * H_) + j;
    const ulonglong2* wrz0 = ((const ulonglong2*)g_Wrz4) + (size_t)head * (KP_ * H_) + j;
    const ull*        wn0  = ((const ull*)g_Wn2) + (size_t)head * (KP_ * H_) + j;
    int cur = 0;

    for (int t = 0; t < T_; t++) {
        if (tid < 256) {
            int d = tid >> 3, bb = tid & 7;
            float v;
            if (t == 0) v = x_past[((b0 + bb) * T_ + (T_ - 1)) * D_ + d];
            else        v = x_current[((b0 + bb) * T_ + (t - 1)) * D_ + d];
            dec_s[d][bb] = v;
        }
        __syncthreads();

        ull ar01 = BR, ar23 = BR, az01 = BZ, az23 = BZ;
        ull ain01 = BIN, ain23 = BIN, ahn01 = BHN, ahn23 = BHN;

        // gi: folded input projection, 32 iters, prefetch depth 4
        {
            ulonglong2 eb[4];
#pragma unroll
            for (int i = 0; i < 4; i++) eb[i] = Eq[i * H_];
#pragma unroll
            for (int d = 0; d < D_; d++) {
                ulonglong2 w = eb[d & 3];
                eb[d & 3] = Eq[(d + 4) * H_];   // overrun covered by tail pad
                ulonglong2 xv = *(const ulonglong2*)&dec_s[d][bh4];
                ull rr = splat_u(lo_u(w.x));
                ull zz = splat_u(hi_u(w.x));
                ull nn = splat_u(lo_u(w.y));
                fma2(ar01, rr, xv.x);  fma2(ar23, rr, xv.y);
                fma2(az01, zz, xv.x);  fma2(az23, zz, xv.y);
                fma2(ain01, nn, xv.x); fma2(ain23, nn, xv.y);
            }
        }

        // gh: recurrent matmul, 128 k-pairs, prefetch depth 4
        {
            ulonglong2 brz[4]; ull bn2[4];
#pragma unroll
            for (int i = 0; i < 4; i++) { brz[i] = wrz0[i * H_]; bn2[i] = wn0[i * H_]; }
            const ulonglong2* wpf = wrz0 + 4 * H_;
            const ull*        npf = wn0  + 4 * H_;
            const float* hbase = &h_s[cur][0][bh4];
#pragma unroll 1
            for (int kp = 0; kp < KP_; kp += 4) {
#pragma unroll
                for (int u = 0; u < 4; u++) {
                    ulonglong2 w = brz[u]; ull n2 = bn2[u];
                    brz[u] = wpf[u * H_]; bn2[u] = npf[u * H_];
                    const float* hk = hbase + (kp + u) * 16;
                    ulonglong2 h0 = *(const ulonglong2*)hk;
                    ulonglong2 h1 = *(const ulonglong2*)(hk + 8);
                    // k = 2(kp+u)
                    {
                        ull rr = splat_u(lo_u(w.x));
                        ull zz = splat_u(hi_u(w.x));
                        ull nn = splat_u(lo_u(n2));
                        fma2(ar01, rr, h0.x);  fma2(ar23, rr, h0.y);
                        fma2(az01, zz, h0.x);  fma2(az23, zz, h0.y);
                        fma2(ahn01, nn, h0.x); fma2(ahn23, nn, h0.y);
                    }
                    // k = 2(kp+u)+1
                    {
                        ull rr = splat_u(lo_u(w.y));
                        ull zz = splat_u(hi_u(w.y));
                        ull nn = splat_u(hi_u(n2));
                        fma2(ar01, rr, h1.x);  fma2(ar23, rr, h1.y);
                        fma2(az01, zz, h1.x);  fma2(az23, zz, h1.y);
                        fma2(ahn01, nn, h1.x); fma2(ahn23, nn, h1.y);
                    }
                }
                wpf += 4 * H_; npf += 4 * H_;
            }
        }

        // gates + fc partials
        float arf[4] = {lo_f(ar01), hi_f(ar01), lo_f(ar23), hi_f(ar23)};
        float azf[4] = {lo_f(az01), hi_f(az01), lo_f(az23), hi_f(az23)};
        float ainf[4] = {lo_f(ain01), hi_f(ain01), lo_f(ain23), hi_f(ain23)};
        float ahnf[4] = {lo_f(ahn01), hi_f(ahn01), lo_f(ahn23), hi_f(ahn23)};
        float p[4];
#pragma unroll
        for (int bb = 0; bb < 4; bb++) {
            float r = fsigmoid(arf[bb]);
            float u = fsigmoid(azf[bb]);
            float n = ftanh(ainf[bb] + r * ahnf[bb]);
            float hn = n + u * (hp[bb] - n);
            hp[bb] = hn;
            p[bb] = fcw * hn;
        }
        *(float4*)&h_s[cur ^ 1][j][bh4] = make_float4(hp[0], hp[1], hp[2], hp[3]);

        // fc reduction: intra-warp shfl, then cross-warp via smem
#pragma unroll
        for (int bb = 0; bb < 4; bb++) {
#pragma unroll
            for (int off = 16; off > 0; off >>= 1)
                p[bb] += __shfl_down_sync(0xffffffffu, p[bb], off);
        }
        if (lane == 0) {
#pragma unroll
            for (int bb = 0; bb < 4; bb++) red_s[warp][bb] = p[bb];
        }
        __syncthreads();
        if (tid < 8) {
            int w0 = (tid < 4) ? 0 : 8;
            int col = tid & 3;
            float s = fcbv;
#pragma unroll
            for (int w = 0; w < 8; w++) s += red_s[w0 + w][col];
            out[((b0 + tid) * T_ + t) * D_ + head] = s;
        }
        cur ^= 1;
    }
}

// ---------------- launch ----------------
extern "C" void kernel_launch(void* const* d_in, const int* in_sizes, int n_in,
                              void* d_out, int out_size) {
    (void)in_sizes; (void)n_in; (void)out_size;
    const float* x_past    = (const float*)d_in[0];
    const float* x_current = (const float*)d_in[1];
    const float* eps       = (const float*)d_in[2];
    const float* enc_Wih   = (const float*)d_in[3];
    const float* enc_bih   = (const float*)d_in[4];
    const float* enc_Whh   = (const float*)d_in[5];
    const float* enc_bhh   = (const float*)d_in[6];
    const float* enc_mu_w  = (const float*)d_in[7];
    const float* enc_mu_b  = (const float*)d_in[8];
    const float* enc_ls_w  = (const float*)d_in[9];
    const float* enc_ls_b  = (const float*)d_in[10];
    const float* refc_w    = (const float*)d_in[11];
    const float* refc_b    = (const float*)d_in[12];
    const float* Win       = (const float*)d_in[13];
    const float* h_Wih     = (const float*)d_in[14];
    const float* h_bih     = (const float*)d_in[15];
    const float* h_Whh     = (const float*)d_in[16];
    const float* h_bhh     = (const float*)d_in[17];
    const float* fc_w      = (const float*)d_in[18];
    const float* fc_b      = (const float*)d_in[19];
    float* out = (float*)d_out;

    prep_kernel<<<1041, 256>>>(h_Whh, h_Wih, enc_Whh, enc_Wih, enc_mu_w, enc_ls_w, refc_w);
    weff_kernel<<<dim3(32, 3), 256>>>(Win);
    encoder_kernel<<<32, 256>>>(x_past, enc_bih, enc_bhh, eps, enc_mu_b, enc_ls_b,
                                refc_b, out);
    decoder_kernel<<<dim3(32, 4), 512>>>(x_past, x_current, h_bih, h_bhh,
                                         fc_w, fc_b, out);
}

// round 11
// speedup vs baseline: 3.9628x; 1.1517x over previous
#include <cuda_runtime.h>
#include <cstdint>

#define B_ 32
#define T_ 64
#define D_ 32
#define H_ 256
#define Z_ 64
#define G_ 768   // 3*H
#define KP_ 128  // H_/2 (k-pairs)

typedef unsigned long long ull;

// ---------------- scratch (static device memory; no allocations) ----------------
// decoder recurrent weights, pad-free, k-paired:
//   g_Wrz4[head][kp][j] = (r_{2kp}, z_{2kp}, r_{2kp+1}, z_{2kp+1})
//   g_Wn2 [head][kp][j] = (n_{2kp}, n_{2kp+1})
__device__ float4 g_Wrz4[D_ * KP_ * H_ + 8 * H_];
__device__ float2 g_Wn2 [D_ * KP_ * H_ + 8 * H_];
// encoder recurrent, same layout
__device__ float4 g_Erz4[KP_ * H_ + 8 * H_];
__device__ float2 g_En2 [KP_ * H_ + 8 * H_];
__device__ float4 g_WiQ [D_ * H_ + 4 * H_];   // encoder input: [d][j] = (r,z,n,0) (+prefetch pad)
__device__ float  g_WihT[D_ * H_ * G_];       // h_Wih transposed planar: [head][k][g]
__device__ float4 g_Weff4[D_ * D_ * H_ + 4 * H_]; // folded input: [head][d][j] = (r,z,n,0)
__device__ float  g_muT [H_ * Z_];            // enc_mu_w transposed [k][z]
__device__ float  g_lsT [H_ * Z_];            // enc_ls_w transposed [k][z]
__device__ float  g_refcT[Z_ * H_];           // refc_w transposed [z][j]
__device__ float  g_h0  [B_ * H_];            // decoder initial hidden

// ---------------- packed f32x2 helpers ----------------
__device__ __forceinline__ void fma2(ull& d, ull a, ull b) {
    asm("fma.rn.f32x2 %0, %1, %2, %0;" : "+l"(d) : "l"(a), "l"(b));
}
__device__ __forceinline__ void add2(ull& d, ull a) {
    asm("add.rn.f32x2 %0, %0, %1;" : "+l"(d) : "l"(a));
}
__device__ __forceinline__ ull splat2(float x) {
    ull r; unsigned u = __float_as_uint(x);
    asm("mov.b64 %0, {%1, %1};" : "=l"(r) : "r"(u));
    return r;
}
__device__ __forceinline__ ull pack2(float a, float b) {
    ull r;
    asm("mov.b64 %0, {%1, %2};" : "=l"(r) : "r"(__float_as_uint(a)), "r"(__float_as_uint(b)));
    return r;
}
__device__ __forceinline__ ull splat_u(unsigned u) {
    ull r;
    asm("mov.b64 %0, {%1, %1};" : "=l"(r) : "r"(u));
    return r;
}
__device__ __forceinline__ float lo_f(ull v) { return __uint_as_float((unsigned)v); }
__device__ __forceinline__ float hi_f(ull v) { return __uint_as_float((unsigned)(v >> 32)); }
__device__ __forceinline__ unsigned lo_u(ull v) { return (unsigned)v; }
__device__ __forceinline__ unsigned hi_u(ull v) { return (unsigned)(v >> 32); }

// ---------------- fast activations ----------------
__device__ __forceinline__ float fsigmoid(float x) {
    float e = __expf(-x);
    return __fdividef(1.f, 1.f + e);
}
__device__ __forceinline__ float ftanh(float x) {
    float e = __expf(2.f * x);
    return 1.f - __fdividef(2.f, e + 1.f);
}

// ---------------- prep: tiled transposes into paired-split layouts ----------------
__global__ void __launch_bounds__(256) prep_kernel(const float* __restrict__ h_Whh,
                                                   const float* __restrict__ h_Wih,
                                                   const float* __restrict__ enc_Whh,
                                                   const float* __restrict__ enc_Wih,
                                                   const float* __restrict__ mu_w,
                                                   const float* __restrict__ ls_w,
                                                   const float* __restrict__ refc_w) {
    const int bx = blockIdx.x;
    const int tid = threadIdx.x;

    if (bx < 1040) {
        __shared__ float tile[3][64][64];   // XOR-swizzled: [g][jj][(kk+jj)&63], 48KB
        const float* src;
        int jt, kt, mode;                   // mode 0: paired-split out, 1: planar out
        float4* drz = nullptr; float2* dn2 = nullptr;
        float*  dstp = nullptr;
        if (bx < 512) {
            int head = bx >> 4; jt = (bx >> 2) & 3; kt = bx & 3; mode = 0;
            src = h_Whh + (size_t)head * (G_ * H_);
            drz = g_Wrz4 + (size_t)head * (KP_ * H_);
            dn2 = g_Wn2  + (size_t)head * (KP_ * H_);
        } else if (bx < 1024) {
            int e = bx - 512;
            int head = e >> 4; jt = (e >> 2) & 3; kt = e & 3; mode = 1;
            src = h_Wih + (size_t)head * (G_ * H_);
            dstp = g_WihT + (size_t)head * (H_ * G_);
        } else {
            int e = bx - 1024;
            jt = (e >> 2) & 3; kt = e & 3; mode = 0;
            src = enc_Whh;
            drz = g_Erz4; dn2 = g_En2;
        }
        for (int g = 0; g < 3; g++) {
            for (int i = tid; i < 64 * 64; i += 256) {
                int jj = i >> 6, kk = i & 63;
                tile[g][jj][(kk + jj) & 63] =
                    src[(size_t)(g * H_ + jt * 64 + jj) * H_ + kt * 64 + kk];
            }
        }
        __syncthreads();
        if (mode == 0) {
            for (int i = tid; i < 32 * 64; i += 256) {
                int kkp = i >> 6, jj = i & 63;
                int c0 = (2 * kkp + jj) & 63, c1 = (2 * kkp + 1 + jj) & 63;
                float r0 = tile[0][jj][c0], r1 = tile[0][jj][c1];
                float z0 = tile[1][jj][c0], z1 = tile[1][jj][c1];
                float n0 = tile[2][jj][c0], n1 = tile[2][jj][c1];
                size_t idx = (size_t)(kt * 32 + kkp) * H_ + jt * 64 + jj;
                drz[idx] = make_float4(r0, z0, r1, z1);
                dn2[idx] = make_float2(n0, n1);
            }
        } else {
            for (int g = 0; g < 3; g++) {
                for (int i = tid; i < 64 * 64; i += 256) {
                    int kk = i >> 6, jj = i & 63;
                    dstp[(size_t)(kt * 64 + kk) * G_ + g * H_ + jt * 64 + jj] =
                        tile[g][jj][(kk + jj) & 63];
                }
            }
        }
    } else {
        for (int i = tid; i < D_ * H_; i += 256) {          // g_WiQ[d][j]
            int d = i >> 8, j = i & 255;
            g_WiQ[i] = make_float4(enc_Wih[(0 * H_ + j) * D_ + d],
                                   enc_Wih[(1 * H_ + j) * D_ + d],
                                   enc_Wih[(2 * H_ + j) * D_ + d], 0.f);
        }
        for (int i = tid; i < H_ * Z_; i += 256) {
            int k = i >> 6, z = i & 63;
            g_muT[i] = mu_w[z * H_ + k];
            g_lsT[i] = ls_w[z * H_ + k];
        }
        for (int i = tid; i < Z_ * H_; i += 256) {
            int z = i >> 8, j = i & 255;
            g_refcT[i] = refc_w[j * Z_ + z];
        }
    }
}

// ---------------- Weff[head][d][j] = (r,z,n,0) folded input weights ----------------
__global__ void __launch_bounds__(256) weff_kernel(const float* __restrict__ Win) {
    const int head = blockIdx.x;
    const int g = blockIdx.y * 256 + threadIdx.x;    // blockIdx.y in [0,3)
    __shared__ float win_s[D_ * H_];                 // 32 KB
    for (int i = threadIdx.x; i < D_ * H_; i += 256)
        win_s[i] = Win[head * (D_ * H_) + i];
    __syncthreads();

    float acc[D_];
#pragma unroll
    for (int d = 0; d < D_; d++) acc[d] = 0.f;

    const float* wt = g_WihT + (size_t)head * (H_ * G_);
#pragma unroll 4
    for (int k = 0; k < H_; k++) {
        float wv = wt[(size_t)k * G_ + g];
#pragma unroll
        for (int d = 0; d < D_; d++) acc[d] += win_s[d * H_ + k] * wv;
    }
    const int gate = g >> 8, jj = g & 255;
    float* o = (float*)(g_Weff4 + (size_t)head * (D_ * H_));
#pragma unroll
    for (int d = 0; d < D_; d++) o[(d * H_ + jj) * 4 + gate] = acc[d];
}

// ---------------- encoder GRU + latent: one CTA per batch, 512 threads (j x khalf) ----------------
__global__ void __launch_bounds__(512, 1) encoder_kernel(const float* __restrict__ x_past,
                                                         const float* __restrict__ bih,
                                                         const float* __restrict__ bhh,
                                                         const float* __restrict__ eps,
                                                         const float* __restrict__ mu_b,
                                                         const float* __restrict__ ls_b,
                                                         const float* __restrict__ refc_b,
                                                         float* __restrict__ out) {
    const int b = blockIdx.x;
    const int tid = threadIdx.x;
    const int j = tid & 255;
    const int kh = tid >> 8;               // k-half
    __shared__ float h_s[2][H_];
    __shared__ float x_s[D_];
    __shared__ float z_s[Z_];
    __shared__ ull xch0[256];              // khalf1 -> khalf0: arz partial
    __shared__ ull xch1[256];              // khalf1 -> khalf0: (ain, ahn) partial

    const float br  = bih[j] + bhh[j];
    const float bz  = bih[H_ + j] + bhh[H_ + j];
    const float bin = bih[2 * H_ + j];
    const float bhn = bhh[2 * H_ + j];

    const ulonglong2* WiQ2 = ((const ulonglong2*)g_WiQ) + (kh * 16) * H_ + j;
    const ulonglong2* wrz0 = ((const ulonglong2*)g_Erz4) + (kh * 64) * H_ + j;
    const ull*        wn0  = ((const ull*)g_En2) + (kh * 64) * H_ + j;

    float hp = 0.f;
    if (tid < 256) h_s[0][tid] = 0.f;
    int cur = 0;

    for (int t = 0; t < T_; t++) {
        __syncthreads();
        if (tid < D_) x_s[tid] = x_past[(b * T_ + t) * D_ + tid];
        __syncthreads();

        ull arz = kh ? 0ull : pack2(br, bz);
        float ain = kh ? 0.f : bin;
        float ahn = kh ? 0.f : bhn;

        // gi: 16 local d iters, prefetch depth 4
        {
            ulonglong2 wb[4];
#pragma unroll
            for (int i = 0; i < 4; i++) wb[i] = WiQ2[i * H_];
#pragma unroll
            for (int dd = 0; dd < 16; dd++) {
                ulonglong2 w = wb[dd & 3];
                wb[dd & 3] = WiQ2[(dd + 4) * H_];   // pad covers overrun
                float xv = x_s[kh * 16 + dd];
                fma2(arz, w.x, splat2(xv));
                ain += lo_f(w.y) * xv;
            }
        }

        // gh: 64 local k-pairs, prefetch depth 8
        {
            ulonglong2 brz[8]; ull bn2[8];
#pragma unroll
            for (int i = 0; i < 8; i++) { brz[i] = wrz0[i * H_]; bn2[i] = wn0[i * H_]; }
            const ulonglong2* wpf = wrz0 + 8 * H_;
            const ull*        npf = wn0  + 8 * H_;
            const float* hrow = h_s[cur] + kh * 128;
#pragma unroll 1
            for (int kp = 0; kp < 64; kp += 8) {
#pragma unroll
                for (int u = 0; u < 8; u++) {
                    ulonglong2 w = brz[u]; ull n2 = bn2[u];
                    brz[u] = wpf[u * H_]; bn2[u] = npf[u * H_];
                    float2 h2 = *(const float2*)&hrow[(kp + u) * 2];
                    fma2(arz, w.x, splat2(h2.x));
                    fma2(arz, w.y, splat2(h2.y));
                    ahn += lo_f(n2) * h2.x;
                    ahn += hi_f(n2) * h2.y;
                }
                wpf += 8 * H_; npf += 8 * H_;
            }
        }

        if (kh == 1) { xch0[j] = arz; xch1[j] = pack2(ain, ahn); }
        __syncthreads();
        if (kh == 0) {
            add2(arz, xch0[j]);
            ull o = xch1[j];
            ain += lo_f(o); ahn += hi_f(o);
            float r = fsigmoid(lo_f(arz));
            float u = fsigmoid(hi_f(arz));
            float n = ftanh(ain + r * ahn);
            hp = n + u * (hp - n);
            h_s[cur ^ 1][j] = hp;
        }
        cur ^= 1;
    }
    __syncthreads();

    // --- latent: mu/logsig/z/h0 ---
    if (tid < Z_) {
        float m = mu_b[tid], l = ls_b[tid];
#pragma unroll 8
        for (int k = 0; k < H_; k++) {
            float hv = h_s[cur][k];
            m += g_muT[k * Z_ + tid] * hv;
            l += g_lsT[k * Z_ + tid] * hv;
        }
        out[B_ * T_ * D_ + b * Z_ + tid] = m;                    // mu
        out[B_ * T_ * D_ + B_ * Z_ + b * Z_ + tid] = l;          // logsig
        z_s[tid] = m + eps[b * Z_ + tid] * __expf(l);
    }
    __syncthreads();

    if (tid < 256) {
        float a = refc_b[tid];
#pragma unroll 8
        for (int z = 0; z < Z_; z++) a += g_refcT[z * H_ + tid] * z_s[z];
        g_h0[b * H_ + tid] = ftanh(a);
    }
}

// ---------------- fused decoder: 32 heads x 4 batch-groups of 8 ----------------
// 512 threads = (j in [0,256)) x (k-half in {0,1}); each thread accumulates ALL
// 8 batches over its k-half, so every weight fetch feeds 8 batches (2x R10).
// Cross-half combine via coalesced smem exchange each step.
__global__ void __launch_bounds__(512, 1) decoder_kernel(const float* __restrict__ x_past,
                                                         const float* __restrict__ x_current,
                                                         const float* __restrict__ h_bih,
                                                         const float* __restrict__ h_bhh,
                                                         const float* __restrict__ fc_w,
                                                         const float* __restrict__ fc_b,
                                                         float* __restrict__ out) {
    const int head = blockIdx.x;
    const int b0 = blockIdx.y * 8;
    const int tid = threadIdx.x;
    const int j = tid & 255;
    const int kh = tid >> 8;                     // k-half; also epilogue batch-half
    const int lane = tid & 31, warp = tid >> 5;  // warps 0-7: kh0 (batches 0-3), 8-15: kh1 (4-7)

    __shared__ __align__(16) float h_s[2][H_][8];   // [buf][k][batch] 16KB
    __shared__ __align__(16) float dec_s[D_][8];    // [d][batch]
    __shared__ ull  xch[2][8][256];                 // [half][slot][j] 32KB, coalesced
    __shared__ float red_s[16][4];                  // [warp][local batch]

    const float* bih = h_bih + head * G_;
    const float* bhh = h_bhh + head * G_;
    const float br  = bih[j] + bhh[j];
    const float bz  = bih[H_ + j] + bhh[H_ + j];
    const float bin = bih[2 * H_ + j];
    const float bhn = bhh[2 * H_ + j];
    const float fcw = fc_w[head * H_ + j];
    const float fcbv = fc_b[head];
    const ull BR = splat2(br), BZ = splat2(bz), BIN = splat2(bin), BHN = splat2(bhn);

    // my 4 epilogue batches: kh*4 .. kh*4+3
    float hp[4];
#pragma unroll
    for (int bb = 0; bb < 4; bb++) hp[bb] = g_h0[(b0 + kh * 4 + bb) * H_ + j];
    *(float4*)&h_s[0][j][kh * 4] = make_float4(hp[0], hp[1], hp[2], hp[3]);

    const ulonglong2* Eq   = ((const ulonglong2*)g_Weff4) + (size_t)head * (D_ * H_) + (kh * 16) * H_ + j;
    const ulonglong2* wrz0 = ((const ulonglong2*)g_Wrz4) + (size_t)head * (KP_ * H_) + (kh * 64) * H_ + j;
    const ull*        wn0  = ((const ull*)g_Wn2) + (size_t)head * (KP_ * H_) + (kh * 64) * H_ + j;
    const int mp = kh * 2;        // pairs I finalize
    const int op = 2 - mp;        // pairs the other half finalizes
    int cur = 0;

    for (int t = 0; t < T_; t++) {
        if (tid < 256) {
            int d = tid >> 3, bb = tid & 7;
            float v;
            if (t == 0) v = x_past[((b0 + bb) * T_ + (T_ - 1)) * D_ + d];
            else        v = x_current[((b0 + bb) * T_ + (t - 1)) * D_ + d];
            dec_s[d][bb] = v;
        }
        __syncthreads();   // dec_s & h_s[cur] ready; xch/red_s reusable

        // accumulators: 4 batch-pairs per gate-group; bias only on my pairs
        ull ar[4], az[4], ain[4], ahn[4];
#pragma unroll
        for (int p = 0; p < 4; p++) {
            bool mine = (p >> 1) == kh;
            ar[p]  = mine ? BR  : 0ull;
            az[p]  = mine ? BZ  : 0ull;
            ain[p] = mine ? BIN : 0ull;
            ahn[p] = mine ? BHN : 0ull;
        }

        // gi: 16 local d iters, prefetch depth 4
        {
            ulonglong2 eb[4];
#pragma unroll
            for (int i = 0; i < 4; i++) eb[i] = Eq[i * H_];
#pragma unroll
            for (int dd = 0; dd < 16; dd++) {
                ulonglong2 w = eb[dd & 3];
                eb[dd & 3] = Eq[(dd + 4) * H_];          // pad covers overrun
                int d = kh * 16 + dd;
                ulonglong2 x01 = *(const ulonglong2*)&dec_s[d][0];
                ulonglong2 x23 = *(const ulonglong2*)&dec_s[d][4];
                ull rr = splat_u(lo_u(w.x));
                ull zz = splat_u(hi_u(w.x));
                ull nn = splat_u(lo_u(w.y));
                fma2(ar[0], rr, x01.x);  fma2(ar[1], rr, x01.y);
                fma2(ar[2], rr, x23.x);  fma2(ar[3], rr, x23.y);
                fma2(az[0], zz, x01.x);  fma2(az[1], zz, x01.y);
                fma2(az[2], zz, x23.x);  fma2(az[3], zz, x23.y);
                fma2(ain[0], nn, x01.x); fma2(ain[1], nn, x01.y);
                fma2(ain[2], nn, x23.x); fma2(ain[3], nn, x23.y);
            }
        }

        // gh: 64 local k-pairs, prefetch depth 4
        {
            ulonglong2 brz[4]; ull bn2[4];
#pragma unroll
            for (int i = 0; i < 4; i++) { brz[i] = wrz0[i * H_]; bn2[i] = wn0[i * H_]; }
            const ulonglong2* wpf = wrz0 + 4 * H_;
            const ull*        npf = wn0  + 4 * H_;
            const float* hbase = &h_s[cur][kh * 128][0];
#pragma unroll 1
            for (int kp = 0; kp < 64; kp += 4) {
#pragma unroll
                for (int u = 0; u < 4; u++) {
                    ulonglong2 w = brz[u]; ull n2 = bn2[u];
                    brz[u] = wpf[u * H_]; bn2[u] = npf[u * H_];
                    const float* hk = hbase + (kp + u) * 16;
                    ulonglong2 ha = *(const ulonglong2*)hk;        // k, batches 0-3
                    ulonglong2 hb = *(const ulonglong2*)(hk + 4);  // k, batches 4-7
                    ulonglong2 hc = *(const ulonglong2*)(hk + 8);  // k+1, batches 0-3
                    ulonglong2 hd = *(const ulonglong2*)(hk + 12); // k+1, batches 4-7
                    {   // k
                        ull rr = splat_u(lo_u(w.x));
                        ull zz = splat_u(hi_u(w.x));
                        ull nn = splat_u(lo_u(n2));
                        fma2(ar[0], rr, ha.x);  fma2(ar[1], rr, ha.y);
                        fma2(ar[2], rr, hb.x);  fma2(ar[3], rr, hb.y);
                        fma2(az[0], zz, ha.x);  fma2(az[1], zz, ha.y);
                        fma2(az[2], zz, hb.x);  fma2(az[3], zz, hb.y);
                        fma2(ahn[0], nn, ha.x); fma2(ahn[1], nn, ha.y);
                        fma2(ahn[2], nn, hb.x); fma2(ahn[3], nn, hb.y);
                    }
                    {   // k+1
                        ull rr = splat_u(lo_u(w.y));
                        ull zz = splat_u(hi_u(w.y));
                        ull nn = splat_u(hi_u(n2));
                        fma2(ar[0], rr, hc.x);  fma2(ar[1], rr, hc.y);
                        fma2(ar[2], rr, hd.x);  fma2(ar[3], rr, hd.y);
                        fma2(az[0], zz, hc.x);  fma2(az[1], zz, hc.y);
                        fma2(az[2], zz, hd.x);  fma2(az[3], zz, hd.y);
                        fma2(ahn[0], nn, hc.x); fma2(ahn[1], nn, hc.y);
                        fma2(ahn[2], nn, hd.x); fma2(ahn[3], nn, hd.y);
                    }
                }
                wpf += 4 * H_; npf += 4 * H_;
            }
        }

        // exchange: hand my partials for the OTHER half's pairs over (coalesced)
        xch[kh][0][j] = ar[op];   xch[kh][1][j] = ar[op + 1];
        xch[kh][2][j] = az[op];   xch[kh][3][j] = az[op + 1];
        xch[kh][4][j] = ain[op];  xch[kh][5][j] = ain[op + 1];
        xch[kh][6][j] = ahn[op];  xch[kh][7][j] = ahn[op + 1];
        __syncthreads();
        const int oh = 1 - kh;
        add2(ar[mp],  xch[oh][0][j]);  add2(ar[mp + 1],  xch[oh][1][j]);
        add2(az[mp],  xch[oh][2][j]);  add2(az[mp + 1],  xch[oh][3][j]);
        add2(ain[mp], xch[oh][4][j]);  add2(ain[mp + 1], xch[oh][5][j]);
        add2(ahn[mp], xch[oh][6][j]);  add2(ahn[mp + 1], xch[oh][7][j]);

        // epilogue for my 4 batches
        float arf[4]  = {lo_f(ar[mp]),  hi_f(ar[mp]),  lo_f(ar[mp + 1]),  hi_f(ar[mp + 1])};
        float azf[4]  = {lo_f(az[mp]),  hi_f(az[mp]),  lo_f(az[mp + 1]),  hi_f(az[mp + 1])};
        float ainf[4] = {lo_f(ain[mp]), hi_f(ain[mp]), lo_f(ain[mp + 1]), hi_f(ain[mp + 1])};
        float ahnf[4] = {lo_f(ahn[mp]), hi_f(ahn[mp]), lo_f(ahn[mp + 1]), hi_f(ahn[mp + 1])};
        float p[4];
#pragma unroll
        for (int bb = 0; bb < 4; bb++) {
            float r = fsigmoid(arf[bb]);
            float u = fsigmoid(azf[bb]);
            float n = ftanh(ainf[bb] + r * ahnf[bb]);
            float hn = n + u * (hp[bb] - n);
            hp[bb] = hn;
            p[bb] = fcw * hn;
        }
        *(float4*)&h_s[cur ^ 1][j][kh * 4] = make_float4(hp[0], hp[1], hp[2], hp[3]);

        // fc reduction: intra-warp shfl, then cross-warp via smem
#pragma unroll
        for (int bb = 0; bb < 4; bb++) {
#pragma unroll
            for (int off = 16; off > 0; off >>= 1)
                p[bb] += __shfl_down_sync(0xffffffffu, p[bb], off);
        }
        if (lane == 0) {
#pragma unroll
            for (int bb = 0; bb < 4; bb++) red_s[warp][bb] = p[bb];
        }
        __syncthreads();
        if (tid < 8) {
            int w0 = (tid < 4) ? 0 : 8;     // batches 0-3 live in warps 0-7 (kh0)
            int col = tid & 3;
            float s = fcbv;
#pragma unroll
            for (int w = 0; w < 8; w++) s += red_s[w0 + w][col];
            out[((b0 + tid) * T_ + t) * D_ + head] = s;
        }
        cur ^= 1;
    }
}

// ---------------- launch ----------------
extern "C" void kernel_launch(void* const* d_in, const int* in_sizes, int n_in,
                              void* d_out, int out_size) {
    (void)in_sizes; (void)n_in; (void)out_size;
    const float* x_past    = (const float*)d_in[0];
    const float* x_current = (const float*)d_in[1];
    const float* eps       = (const float*)d_in[2];
    const float* enc_Wih   = (const float*)d_in[3];
    const float* enc_bih   = (const float*)d_in[4];
    const float* enc_Whh   = (const float*)d_in[5];
    const float* enc_bhh   = (const float*)d_in[6];
    const float* enc_mu_w  = (const float*)d_in[7];
    const float* enc_mu_b  = (const float*)d_in[8];
    const float* enc_ls_w  = (const float*)d_in[9];
    const float* enc_ls_b  = (const float*)d_in[10];
    const float* refc_w    = (const float*)d_in[11];
    const float* refc_b    = (const float*)d_in[12];
    const float* Win       = (const float*)d_in[13];
    const float* h_Wih     = (const float*)d_in[14];
    const float* h_bih     = (const float*)d_in[15];
    const float* h_Whh     = (const float*)d_in[16];
    const float* h_bhh     = (const float*)d_in[17];
    const float* fc_w      = (const float*)d_in[18];
    const float* fc_b      = (const float*)d_in[19];
    float* out = (float*)d_out;

    prep_kernel<<<1041, 256>>>(h_Whh, h_Wih, enc_Whh, enc_Wih, enc_mu_w, enc_ls_w, refc_w);
    weff_kernel<<<dim3(32, 3), 256>>>(Win);
    encoder_kernel<<<32, 512>>>(x_past, enc_bih, enc_bhh, eps, enc_mu_b, enc_ls_b,
                                refc_b, out);
    decoder_kernel<<<dim3(32, 4), 512>>>(x_past, x_current, h_bih, h_bhh,
                                         fc_w, fc_b, out);
}